// round 11
// baseline (speedup 1.0000x reference)
#include <cuda_runtime.h>
#include <cuda_fp16.h>
#include <cstdint>

#define SQ 4096      // sequence length S
#define ND 1024      // model dim N
#define FD 4096      // ffn dim 4N

// ---------------- scratch (allocation-free: static device globals) ----------
__device__ float  g_xn [(size_t)SQ * ND];           // fp32 normed x (residual)
__device__ __half g_xnh[(size_t)SQ * ND];           // fp16 normed x (GEMM A)
__device__ __half g_qh [(size_t)SQ * ND];
__device__ __half g_kh [(size_t)SQ * ND];
__device__ __half g_vT [(size_t)ND * SQ];           // v transposed [n][s]
__device__ float  g_s  [(size_t)SQ * SQ];           // fp32 scores
__device__ __half g_p  [(size_t)SQ * SQ];           // fp16 probs
__device__ __half g_h  [(size_t)SQ * ND];
__device__ __half g_mid[(size_t)SQ * FD];
// pre-transposed fp16 weights WT[n][k]
__device__ __half g_wqT[(size_t)ND * ND];
__device__ __half g_wkT[(size_t)ND * ND];
__device__ __half g_wvT[(size_t)ND * ND];
__device__ __half g_w1T[(size_t)FD * ND];
__device__ __half g_w2T[(size_t)ND * FD];

// ---------------- helpers ----------------
__device__ __forceinline__ float warpSum(float v) {
    #pragma unroll
    for (int o = 16; o; o >>= 1) v += __shfl_xor_sync(0xffffffffu, v, o);
    return v;
}
__device__ __forceinline__ float warpMax(float v) {
    #pragma unroll
    for (int o = 16; o; o >>= 1) v = fmaxf(v, __shfl_xor_sync(0xffffffffu, v, o));
    return v;
}
__device__ __forceinline__ void cp_async16(void* smem_dst, const void* gmem_src) {
    uint32_t s = (uint32_t)__cvta_generic_to_shared(smem_dst);
    asm volatile("cp.async.cg.shared.global [%0], [%1], 16;" :: "r"(s), "l"(gmem_src));
}
__device__ __forceinline__ void cp_commit() {
    asm volatile("cp.async.commit_group;" ::: "memory");
}
template<int NN>
__device__ __forceinline__ void cp_wait() {
    asm volatile("cp.async.wait_group %0;" :: "n"(NN) : "memory");
}
__device__ __forceinline__ uint32_t smem_u32(const void* p) {
    return (uint32_t)__cvta_generic_to_shared(p);
}
__device__ __forceinline__ void mma_f16(float* c, const uint32_t* a, const uint32_t* b) {
    asm volatile(
        "mma.sync.aligned.m16n8k16.row.col.f32.f16.f16.f32 "
        "{%0,%1,%2,%3}, {%4,%5,%6,%7}, {%8,%9}, {%0,%1,%2,%3};"
        : "+f"(c[0]), "+f"(c[1]), "+f"(c[2]), "+f"(c[3])
        : "r"(a[0]), "r"(a[1]), "r"(a[2]), "r"(a[3]), "r"(b[0]), "r"(b[1]));
}
__device__ __forceinline__ void ldm_x4(uint32_t& r0, uint32_t& r1, uint32_t& r2, uint32_t& r3,
                                       uint32_t a) {
    asm volatile("ldmatrix.sync.aligned.m8n8.x4.shared.b16 {%0,%1,%2,%3}, [%4];"
                 : "=r"(r0), "=r"(r1), "=r"(r2), "=r"(r3) : "r"(a));
}

// ---------------- weight prep: W[K,N] fp32 -> WT[N,K] fp16 ------------------
__global__ __launch_bounds__(256) void wprep_kernel(const float* __restrict__ W,
                                                    __half* __restrict__ T,
                                                    int K, int N) {
    __shared__ float tile[32][33];
    int n0 = blockIdx.x * 32;
    int k0 = blockIdx.y * 32;
    int tx = threadIdx.x & 31;
    int ty = threadIdx.x >> 5;     // 0..7
    #pragma unroll
    for (int i = 0; i < 4; i++) {
        int r = ty + i * 8;
        tile[r][tx] = W[(size_t)(k0 + r) * N + n0 + tx];
    }
    __syncthreads();
    #pragma unroll
    for (int i = 0; i < 4; i++) {
        int r = ty + i * 8;
        T[(size_t)(n0 + r) * K + k0 + tx] = __float2half_rn(tile[tx][r]);
    }
}

// ---------------- LayerNorm: fp32 out + fp16 out ----------------------------
__global__ __launch_bounds__(256) void ln_kernel(const float* __restrict__ x,
                                                 const float* __restrict__ g,
                                                 const float* __restrict__ b) {
    int row = blockIdx.x;
    int t = threadIdx.x;
    const float4* xr = (const float4*)(x + (size_t)row * ND);
    float4 xv = xr[t];
    float s1 = xv.x + xv.y + xv.z + xv.w;
    float s2 = xv.x*xv.x + xv.y*xv.y + xv.z*xv.z + xv.w*xv.w;

    __shared__ float shA[8], shB[8];
    s1 = warpSum(s1); s2 = warpSum(s2);
    if ((t & 31) == 0) { shA[t >> 5] = s1; shB[t >> 5] = s2; }
    __syncthreads();
    if (t < 32) {
        float a = (t < 8) ? shA[t] : 0.0f;
        float c = (t < 8) ? shB[t] : 0.0f;
        a = warpSum(a); c = warpSum(c);
        if (t == 0) { shA[0] = a; shB[0] = c; }
    }
    __syncthreads();
    float mu  = shA[0] * (1.0f / ND);
    float var = shB[0] * (1.0f / ND) - mu * mu;
    float rstd = rsqrtf(var + 1e-5f);

    float4 gv = ((const float4*)g)[t];
    float4 bv = ((const float4*)b)[t];
    float4 o;
    o.x = (xv.x - mu) * rstd * gv.x + bv.x;
    o.y = (xv.y - mu) * rstd * gv.y + bv.y;
    o.z = (xv.z - mu) * rstd * gv.z + bv.z;
    o.w = (xv.w - mu) * rstd * gv.w + bv.w;
    size_t idx = (size_t)row * ND + t * 4;
    *(float4*)(g_xn + idx) = o;
    *(__half2*)(g_xnh + idx)     = __floats2half2_rn(o.x, o.y);
    *(__half2*)(g_xnh + idx + 2) = __floats2half2_rn(o.z, o.w);
}

// ---------------- Softmax: fp32 scores -> fp16 probs ------------------------
__global__ __launch_bounds__(256) void softmax_kernel() {
    int row = blockIdx.x;
    int t = threadIdx.x;
    const float4* r = (const float4*)(g_s + (size_t)row * SQ);
    float4 v[4];
    float mx = -1e30f;
    #pragma unroll
    for (int i = 0; i < 4; i++) {
        v[i] = r[t + i * 256];
        mx = fmaxf(mx, fmaxf(fmaxf(v[i].x, v[i].y), fmaxf(v[i].z, v[i].w)));
    }
    __shared__ float shA[8], shB[8];
    mx = warpMax(mx);
    if ((t & 31) == 0) shA[t >> 5] = mx;
    __syncthreads();
    if (t < 32) {
        float a = (t < 8) ? shA[t] : -1e30f;
        a = warpMax(a);
        if (t == 0) shA[0] = a;
    }
    __syncthreads();
    mx = shA[0];

    float sum = 0.0f;
    #pragma unroll
    for (int i = 0; i < 4; i++) {
        v[i].x = __expf(v[i].x - mx);
        v[i].y = __expf(v[i].y - mx);
        v[i].z = __expf(v[i].z - mx);
        v[i].w = __expf(v[i].w - mx);
        sum += v[i].x + v[i].y + v[i].z + v[i].w;
    }
    sum = warpSum(sum);
    if ((t & 31) == 0) shB[t >> 5] = sum;
    __syncthreads();
    if (t < 32) {
        float a = (t < 8) ? shB[t] : 0.0f;
        a = warpSum(a);
        if (t == 0) shB[0] = a;
    }
    __syncthreads();
    float inv = 1.0f / shB[0];
    #pragma unroll
    for (int i = 0; i < 4; i++) {
        size_t idx = (size_t)row * SQ + (t + i * 256) * 4;
        *(__half2*)(g_p + idx)     = __floats2half2_rn(v[i].x * inv, v[i].y * inv);
        *(__half2*)(g_p + idx + 2) = __floats2half2_rn(v[i].z * inv, v[i].w * inv);
    }
}

// ---------------- fp16 tensor-core GEMM (BT layout, ldmatrix) ---------------
// C[M,Nn] = act(scale*(A @ B^T) + bias) (+resid)
// A [M,K] fp16 row-major, B [Nn,K] fp16 row-major.
// MODE 0: fp32 out Cf (scale, +resid). MODE 1: fp16 out Ch (bias, act).
// MODE 2: fp16 out transposed Ch[col*M + row] (bias).
// Tile: 128x128, 4 warps (64x64 each), BK=32, 3-stage cp.async,
// single __syncthreads per k-tile. Fragments via non-trans ldmatrix.x4.
template<int MODE, int ACT, bool RES>
__global__ __launch_bounds__(128, 2) void hgemm_kernel(
    const __half* __restrict__ A, const __half* __restrict__ B,
    const float* __restrict__ bias, const float* __restrict__ resid,
    float* __restrict__ Cf, __half* __restrict__ Ch,
    int M, int Nn, int K, float scale)
{
    constexpr int BK = 32;
    constexpr int PITCH = 40;          // smem row pitch in halves (conflict-free ldmatrix)
    constexpr int TST = 128 * PITCH;   // halves per tile-stage

    extern __shared__ __half smem[];
    __half* Asm = smem;
    __half* Bsm = smem + 3 * TST;

    int tid  = threadIdx.x;
    int wid  = tid >> 5;
    int lane = tid & 31;
    int grp  = lane >> 2;
    int tig  = lane & 3;
    int wm = (wid & 1) * 64;
    int wn = (wid >> 1) * 64;
    int bm = blockIdx.y * 128;
    int bn = blockIdx.x * 128;

    float acc[4][8][4];
    #pragma unroll
    for (int i = 0; i < 4; i++)
        #pragma unroll
        for (int j = 0; j < 8; j++)
            #pragma unroll
            for (int c = 0; c < 4; c++) acc[i][j][c] = 0.0f;

    auto loadTile = [&](int s, int k0) {
        __half* As = Asm + s * TST;
        __half* Bs = Bsm + s * TST;
        #pragma unroll
        for (int it = 0; it < 4; it++) {
            int idx = tid + it * 128;
            int r = idx >> 2;
            int ch = (idx & 3) << 3;
            cp_async16(As + r * PITCH + ch, A + (size_t)(bm + r) * K + k0 + ch);
        }
        #pragma unroll
        for (int it = 0; it < 4; it++) {
            int idx = tid + it * 128;
            int r = idx >> 2;
            int ch = (idx & 3) << 3;
            cp_async16(Bs + r * PITCH + ch, B + (size_t)(bn + r) * K + k0 + ch);
        }
        cp_commit();
    };

    int nt = K / BK;
    loadTile(0, 0);
    loadTile(1, BK);

    int s = 0, sl = 2;
    for (int t = 0; t < nt; t++) {
        if (t + 1 < nt) cp_wait<1>(); else cp_wait<0>();
        __syncthreads();

        const __half* As = Asm + s * TST;
        const __half* Bs = Bsm + s * TST;

        #pragma unroll
        for (int ks = 0; ks < 2; ks++) {
            uint32_t af[4][4];
            uint32_t bf[8][2];
            #pragma unroll
            for (int mi = 0; mi < 4; mi++) {
                int row = wm + mi * 16 + (lane & 15);
                uint32_t addr = smem_u32(As + row * PITCH + ks * 16 + (lane >> 4) * 8);
                ldm_x4(af[mi][0], af[mi][1], af[mi][2], af[mi][3], addr);
            }
            #pragma unroll
            for (int nj = 0; nj < 4; nj++) {
                int row = wn + nj * 16 + (lane & 15);
                uint32_t addr = smem_u32(Bs + row * PITCH + ks * 16 + (lane >> 4) * 8);
                uint32_t r0, r1, r2, r3;
                ldm_x4(r0, r1, r2, r3, addr);
                bf[nj * 2][0]     = r0;   // n  0..8, k  0..8
                bf[nj * 2 + 1][0] = r1;   // n 8..16, k  0..8
                bf[nj * 2][1]     = r2;   // n  0..8, k 8..16
                bf[nj * 2 + 1][1] = r3;   // n 8..16, k 8..16
            }
            #pragma unroll
            for (int mi = 0; mi < 4; mi++)
                #pragma unroll
                for (int ni = 0; ni < 8; ni++)
                    mma_f16(acc[mi][ni], af[mi], bf[ni]);
        }

        if (t + 2 < nt) loadTile(sl, (t + 2) * BK);
        s  = (s  == 2) ? 0 : s + 1;
        sl = (sl == 2) ? 0 : sl + 1;
    }

    // epilogue: c0=(g,2t) c1=(g,2t+1) c2=(g+8,2t) c3=(g+8,2t+1)
    #pragma unroll
    for (int mi = 0; mi < 4; mi++) {
        #pragma unroll
        for (int ni = 0; ni < 8; ni++) {
            int col = bn + wn + ni * 8 + 2 * tig;
            float b0v = bias ? bias[col]     : 0.0f;
            float b1v = bias ? bias[col + 1] : 0.0f;
            #pragma unroll
            for (int rr = 0; rr < 2; rr++) {
                int row = bm + wm + mi * 16 + grp + rr * 8;
                float v0 = acc[mi][ni][rr * 2 + 0] * scale + b0v;
                float v1 = acc[mi][ni][rr * 2 + 1] * scale + b1v;
                if (ACT == 1) {
                    v0 = (v0 > 0.0f) ? v0 : 0.1f * v0;
                    v1 = (v1 > 0.0f) ? v1 : 0.1f * v1;
                }
                if (MODE == 0) {
                    size_t off = (size_t)row * Nn + col;
                    if (RES) { v0 += resid[off]; v1 += resid[off + 1]; }
                    *(float2*)(Cf + off) = make_float2(v0, v1);
                } else if (MODE == 1) {
                    size_t off = (size_t)row * Nn + col;
                    *(__half2*)(Ch + off) = __floats2half2_rn(v0, v1);
                } else {
                    Ch[(size_t)col * M + row]       = __float2half_rn(v0);
                    Ch[(size_t)(col + 1) * M + row] = __float2half_rn(v1);
                }
            }
        }
    }
}

static constexpr int SMEM_H = 6 * 128 * 40 * 2;   // 61440 bytes

// ---------------- host side ----------------
extern "C" void kernel_launch(void* const* d_in, const int* in_sizes, int n_in,
                              void* d_out, int out_size) {
    const float* x      = (const float*)d_in[0];
    const float* norm_g = (const float*)d_in[1];
    const float* norm_b = (const float*)d_in[2];
    const float* Wq = (const float*)d_in[3];
    const float* bq = (const float*)d_in[4];
    const float* Wk = (const float*)d_in[5];
    const float* bk = (const float*)d_in[6];
    const float* Wv = (const float*)d_in[7];
    const float* bv = (const float*)d_in[8];
    const float* W1 = (const float*)d_in[9];
    const float* b1 = (const float*)d_in[10];
    const float* W2 = (const float*)d_in[11];
    const float* b2 = (const float*)d_in[12];
    float* out = (float*)d_out;

    float  *xn, *s;
    __half *xnh, *qh, *kh, *vT, *p, *h, *mid;
    __half *wqT, *wkT, *wvT, *w1T, *w2T;
    cudaGetSymbolAddress((void**)&xn,  g_xn);
    cudaGetSymbolAddress((void**)&s,   g_s);
    cudaGetSymbolAddress((void**)&xnh, g_xnh);
    cudaGetSymbolAddress((void**)&qh,  g_qh);
    cudaGetSymbolAddress((void**)&kh,  g_kh);
    cudaGetSymbolAddress((void**)&vT,  g_vT);
    cudaGetSymbolAddress((void**)&p,   g_p);
    cudaGetSymbolAddress((void**)&h,   g_h);
    cudaGetSymbolAddress((void**)&mid, g_mid);
    cudaGetSymbolAddress((void**)&wqT, g_wqT);
    cudaGetSymbolAddress((void**)&wkT, g_wkT);
    cudaGetSymbolAddress((void**)&wvT, g_wvT);
    cudaGetSymbolAddress((void**)&w1T, g_w1T);
    cudaGetSymbolAddress((void**)&w2T, g_w2T);

    cudaFuncSetAttribute(hgemm_kernel<0,0,false>, cudaFuncAttributeMaxDynamicSharedMemorySize, SMEM_H);
    cudaFuncSetAttribute(hgemm_kernel<0,0,true >, cudaFuncAttributeMaxDynamicSharedMemorySize, SMEM_H);
    cudaFuncSetAttribute(hgemm_kernel<1,0,false>, cudaFuncAttributeMaxDynamicSharedMemorySize, SMEM_H);
    cudaFuncSetAttribute(hgemm_kernel<1,1,false>, cudaFuncAttributeMaxDynamicSharedMemorySize, SMEM_H);
    cudaFuncSetAttribute(hgemm_kernel<2,0,false>, cudaFuncAttributeMaxDynamicSharedMemorySize, SMEM_H);

    // 0. weight prep (transpose + fp16)
    wprep_kernel<<<dim3(ND/32, ND/32), 256>>>(Wq, wqT, ND, ND);
    wprep_kernel<<<dim3(ND/32, ND/32), 256>>>(Wk, wkT, ND, ND);
    wprep_kernel<<<dim3(ND/32, ND/32), 256>>>(Wv, wvT, ND, ND);
    wprep_kernel<<<dim3(FD/32, ND/32), 256>>>(W1, w1T, ND, FD);
    wprep_kernel<<<dim3(ND/32, FD/32), 256>>>(W2, w2T, FD, ND);

    // 1. LayerNorm
    ln_kernel<<<SQ, 256>>>(x, norm_g, norm_b);

    // 2. q/k/v projections  (C = xn @ WT^T), v written transposed
    dim3 gNN(ND/128, SQ/128);           // (8, 32)
    hgemm_kernel<1,0,false><<<gNN, 128, SMEM_H>>>(xnh, wqT, bq, nullptr, nullptr, qh, SQ, ND, ND, 1.0f);
    hgemm_kernel<1,0,false><<<gNN, 128, SMEM_H>>>(xnh, wkT, bk, nullptr, nullptr, kh, SQ, ND, ND, 1.0f);
    hgemm_kernel<2,0,false><<<gNN, 128, SMEM_H>>>(xnh, wvT, bv, nullptr, nullptr, vT, SQ, ND, ND, 1.0f);

    // 3. scores = (k @ q^T)/sqrt(N)  -> fp32 [SQ,SQ]
    dim3 gSS(SQ/128, SQ/128);           // (32, 32)
    hgemm_kernel<0,0,false><<<gSS, 128, SMEM_H>>>(kh, qh, nullptr, nullptr, s, nullptr, SQ, SQ, ND, 0.03125f);

    // 4. softmax -> fp16 probs
    softmax_kernel<<<SQ, 256>>>();

    // 5. h = P @ v   (B = v^T [ND][SQ])
    hgemm_kernel<1,0,false><<<gNN, 128, SMEM_H>>>(p, vT, nullptr, nullptr, nullptr, h, SQ, ND, SQ, 1.0f);

    // 6. mid = leaky_relu(h @ W1 + b1)
    dim3 gNF(FD/128, SQ/128);           // (32, 32)
    hgemm_kernel<1,1,false><<<gNF, 128, SMEM_H>>>(h, w1T, b1, nullptr, nullptr, mid, SQ, FD, ND, 1.0f);

    // 7. out = mid @ W2 + b2 + xn
    hgemm_kernel<0,0,true><<<gNN, 128, SMEM_H>>>(mid, w2T, b2, xn, out, nullptr, SQ, ND, FD, 1.0f);
}

// round 14
// speedup vs baseline: 1.0934x; 1.0934x over previous
#include <cuda_runtime.h>
#include <cuda_fp16.h>
#include <cstdint>

#define SQ 4096      // sequence length S
#define ND 1024      // model dim N
#define FD 4096      // ffn dim 4N

// ---------------- scratch (allocation-free: static device globals) ----------
__device__ float  g_xn [(size_t)SQ * ND];           // fp32 normed x (residual)
__device__ __half g_xnh[(size_t)SQ * ND];           // fp16 normed x (GEMM A)
__device__ __half g_qh [(size_t)SQ * ND];
__device__ __half g_kh [(size_t)SQ * ND];
__device__ __half g_vT [(size_t)ND * SQ];           // v transposed [n][s]
__device__ float  g_s  [(size_t)SQ * SQ];           // fp32 scores
__device__ __half g_p  [(size_t)SQ * SQ];           // fp16 probs
__device__ __half g_h  [(size_t)SQ * ND];
__device__ __half g_mid[(size_t)SQ * FD];
// pre-transposed fp16 weights WT[n][k]
__device__ __half g_wqT[(size_t)ND * ND];
__device__ __half g_wkT[(size_t)ND * ND];
__device__ __half g_wvT[(size_t)ND * ND];
__device__ __half g_w1T[(size_t)FD * ND];
__device__ __half g_w2T[(size_t)ND * FD];

// ---------------- helpers ----------------
__device__ __forceinline__ float warpSum(float v) {
    #pragma unroll
    for (int o = 16; o; o >>= 1) v += __shfl_xor_sync(0xffffffffu, v, o);
    return v;
}
__device__ __forceinline__ float warpMax(float v) {
    #pragma unroll
    for (int o = 16; o; o >>= 1) v = fmaxf(v, __shfl_xor_sync(0xffffffffu, v, o));
    return v;
}
__device__ __forceinline__ void cp_async16(void* smem_dst, const void* gmem_src) {
    uint32_t s = (uint32_t)__cvta_generic_to_shared(smem_dst);
    asm volatile("cp.async.cg.shared.global [%0], [%1], 16;" :: "r"(s), "l"(gmem_src));
}
__device__ __forceinline__ void cp_commit() {
    asm volatile("cp.async.commit_group;" ::: "memory");
}
template<int NN>
__device__ __forceinline__ void cp_wait() {
    asm volatile("cp.async.wait_group %0;" :: "n"(NN) : "memory");
}
__device__ __forceinline__ void mma_f16(float* c, const uint32_t* a, const uint32_t* b) {
    asm volatile(
        "mma.sync.aligned.m16n8k16.row.col.f32.f16.f16.f32 "
        "{%0,%1,%2,%3}, {%4,%5,%6,%7}, {%8,%9}, {%0,%1,%2,%3};"
        : "+f"(c[0]), "+f"(c[1]), "+f"(c[2]), "+f"(c[3])
        : "r"(a[0]), "r"(a[1]), "r"(a[2]), "r"(a[3]), "r"(b[0]), "r"(b[1]));
}

// ---------------- weight prep: W[K,N] fp32 -> WT[N,K] fp16 ------------------
__global__ __launch_bounds__(256) void wprep_kernel(const float* __restrict__ W,
                                                    __half* __restrict__ T,
                                                    int K, int N) {
    __shared__ float tile[32][33];
    int n0 = blockIdx.x * 32;
    int k0 = blockIdx.y * 32;
    int tx = threadIdx.x & 31;
    int ty = threadIdx.x >> 5;     // 0..7
    #pragma unroll
    for (int i = 0; i < 4; i++) {
        int r = ty + i * 8;
        tile[r][tx] = W[(size_t)(k0 + r) * N + n0 + tx];
    }
    __syncthreads();
    #pragma unroll
    for (int i = 0; i < 4; i++) {
        int r = ty + i * 8;
        T[(size_t)(n0 + r) * K + k0 + tx] = __float2half_rn(tile[tx][r]);
    }
}

// ---------------- LayerNorm: fp32 out + fp16 out ----------------------------
__global__ __launch_bounds__(256) void ln_kernel(const float* __restrict__ x,
                                                 const float* __restrict__ g,
                                                 const float* __restrict__ b) {
    int row = blockIdx.x;
    int t = threadIdx.x;
    const float4* xr = (const float4*)(x + (size_t)row * ND);
    float4 xv = xr[t];
    float s1 = xv.x + xv.y + xv.z + xv.w;
    float s2 = xv.x*xv.x + xv.y*xv.y + xv.z*xv.z + xv.w*xv.w;

    __shared__ float shA[8], shB[8];
    s1 = warpSum(s1); s2 = warpSum(s2);
    if ((t & 31) == 0) { shA[t >> 5] = s1; shB[t >> 5] = s2; }
    __syncthreads();
    if (t < 32) {
        float a = (t < 8) ? shA[t] : 0.0f;
        float c = (t < 8) ? shB[t] : 0.0f;
        a = warpSum(a); c = warpSum(c);
        if (t == 0) { shA[0] = a; shB[0] = c; }
    }
    __syncthreads();
    float mu  = shA[0] * (1.0f / ND);
    float var = shB[0] * (1.0f / ND) - mu * mu;
    float rstd = rsqrtf(var + 1e-5f);

    float4 gv = ((const float4*)g)[t];
    float4 bv = ((const float4*)b)[t];
    float4 o;
    o.x = (xv.x - mu) * rstd * gv.x + bv.x;
    o.y = (xv.y - mu) * rstd * gv.y + bv.y;
    o.z = (xv.z - mu) * rstd * gv.z + bv.z;
    o.w = (xv.w - mu) * rstd * gv.w + bv.w;
    size_t idx = (size_t)row * ND + t * 4;
    *(float4*)(g_xn + idx) = o;
    *(__half2*)(g_xnh + idx)     = __floats2half2_rn(o.x, o.y);
    *(__half2*)(g_xnh + idx + 2) = __floats2half2_rn(o.z, o.w);
}

// ---------------- Softmax: fp32 scores -> fp16 probs ------------------------
__global__ __launch_bounds__(256) void softmax_kernel() {
    int row = blockIdx.x;
    int t = threadIdx.x;
    const float4* r = (const float4*)(g_s + (size_t)row * SQ);
    float4 v[4];
    float mx = -1e30f;
    #pragma unroll
    for (int i = 0; i < 4; i++) {
        v[i] = r[t + i * 256];
        mx = fmaxf(mx, fmaxf(fmaxf(v[i].x, v[i].y), fmaxf(v[i].z, v[i].w)));
    }
    __shared__ float shA[8], shB[8];
    mx = warpMax(mx);
    if ((t & 31) == 0) shA[t >> 5] = mx;
    __syncthreads();
    if (t < 32) {
        float a = (t < 8) ? shA[t] : -1e30f;
        a = warpMax(a);
        if (t == 0) shA[0] = a;
    }
    __syncthreads();
    mx = shA[0];

    float sum = 0.0f;
    #pragma unroll
    for (int i = 0; i < 4; i++) {
        v[i].x = __expf(v[i].x - mx);
        v[i].y = __expf(v[i].y - mx);
        v[i].z = __expf(v[i].z - mx);
        v[i].w = __expf(v[i].w - mx);
        sum += v[i].x + v[i].y + v[i].z + v[i].w;
    }
    sum = warpSum(sum);
    if ((t & 31) == 0) shB[t >> 5] = sum;
    __syncthreads();
    if (t < 32) {
        float a = (t < 8) ? shB[t] : 0.0f;
        a = warpSum(a);
        if (t == 0) shB[0] = a;
    }
    __syncthreads();
    float inv = 1.0f / shB[0];
    #pragma unroll
    for (int i = 0; i < 4; i++) {
        size_t idx = (size_t)row * SQ + (t + i * 256) * 4;
        *(__half2*)(g_p + idx)     = __floats2half2_rn(v[i].x * inv, v[i].y * inv);
        *(__half2*)(g_p + idx + 2) = __floats2half2_rn(v[i].z * inv, v[i].w * inv);
    }
}

// ---------------- fp16 tensor-core GEMM -------------------------------------
// C[M,Nn] = act(scale*(A @ B^T) + bias) (+resid)
// A [M,K] fp16 row-major, B [Nn,K] fp16 row-major.
// MODE 0: fp32 out Cf (scale, +resid). MODE 1: fp16 out Ch (bias, act).
// MODE 2: fp16 out transposed Ch[col*M + row] (bias).
// Tile: 128x128, 256 threads = 8 warps (64x32 each), BK=32, 3-stage cp.async,
// single __syncthreads per k-tile, scalar-LDS fragments.
// Small warp tile keeps acc at 64 regs -> ~110 live regs -> clean 2 CTAs/SM
// = 16 warps/SM (2x round-8's latency hiding) with zero spill risk.
template<int MODE, int ACT, bool RES>
__global__ __launch_bounds__(256, 2) void hgemm_kernel(
    const __half* __restrict__ A, const __half* __restrict__ B,
    const float* __restrict__ bias, const float* __restrict__ resid,
    float* __restrict__ Cf, __half* __restrict__ Ch,
    int M, int Nn, int K, float scale)
{
    constexpr int BK = 32;
    constexpr int PITCH = 40;          // smem row pitch in halves (conflict-free)
    constexpr int TST = 128 * PITCH;   // halves per tile-stage

    extern __shared__ __half smem[];
    __half* Asm = smem;
    __half* Bsm = smem + 3 * TST;

    int tid  = threadIdx.x;
    int wid  = tid >> 5;
    int lane = tid & 31;
    int grp  = lane >> 2;
    int tig  = lane & 3;
    int wm = (wid & 1) * 64;      // warp m-offset (2 warps over M)
    int wn = (wid >> 1) * 32;     // warp n-offset (4 warps over N)
    int bm = blockIdx.y * 128;
    int bn = blockIdx.x * 128;

    float acc[4][4][4];
    #pragma unroll
    for (int i = 0; i < 4; i++)
        #pragma unroll
        for (int j = 0; j < 4; j++)
            #pragma unroll
            for (int c = 0; c < 4; c++) acc[i][j][c] = 0.0f;

    auto loadTile = [&](int s, int k0) {
        __half* As = Asm + s * TST;
        __half* Bs = Bsm + s * TST;
        #pragma unroll
        for (int it = 0; it < 2; it++) {
            int idx = tid + it * 256;     // 0..511
            int r = idx >> 2;             // 0..127
            int ch = (idx & 3) << 3;      // half-offset 0,8,16,24
            cp_async16(As + r * PITCH + ch, A + (size_t)(bm + r) * K + k0 + ch);
        }
        #pragma unroll
        for (int it = 0; it < 2; it++) {
            int idx = tid + it * 256;
            int r = idx >> 2;
            int ch = (idx & 3) << 3;
            cp_async16(Bs + r * PITCH + ch, B + (size_t)(bn + r) * K + k0 + ch);
        }
        cp_commit();
    };

    int nt = K / BK;
    loadTile(0, 0);
    loadTile(1, BK);

    int s = 0, sl = 2;
    for (int t = 0; t < nt; t++) {
        if (t + 1 < nt) cp_wait<1>(); else cp_wait<0>();
        __syncthreads();

        const __half* As = Asm + s * TST;
        const __half* Bs = Bsm + s * TST;

        #pragma unroll
        for (int ks = 0; ks < 2; ks++) {
            uint32_t af[4][4];
            uint32_t bf[4][2];
            #pragma unroll
            for (int mi = 0; mi < 4; mi++) {
                const __half* ap = &As[(wm + mi * 16 + grp) * PITCH + ks * 16 + tig * 2];
                af[mi][0] = *(const uint32_t*)(ap);                 // (g,    2t..2t+1)
                af[mi][1] = *(const uint32_t*)(ap + 8 * PITCH);     // (g+8,  2t..2t+1)
                af[mi][2] = *(const uint32_t*)(ap + 8);             // (g,    2t+8..9)
                af[mi][3] = *(const uint32_t*)(ap + 8 * PITCH + 8); // (g+8,  2t+8..9)
            }
            #pragma unroll
            for (int ni = 0; ni < 4; ni++) {
                const __half* bp = &Bs[(wn + ni * 8 + grp) * PITCH + ks * 16 + tig * 2];
                bf[ni][0] = *(const uint32_t*)(bp);                 // (n g, k 2t..2t+1)
                bf[ni][1] = *(const uint32_t*)(bp + 8);             // (n g, k 2t+8..9)
            }
            #pragma unroll
            for (int mi = 0; mi < 4; mi++)
                #pragma unroll
                for (int ni = 0; ni < 4; ni++)
                    mma_f16(acc[mi][ni], af[mi], bf[ni]);
        }

        if (t + 2 < nt) loadTile(sl, (t + 2) * BK);
        s  = (s  == 2) ? 0 : s + 1;
        sl = (sl == 2) ? 0 : sl + 1;
    }

    // epilogue: c0=(g,2t) c1=(g,2t+1) c2=(g+8,2t) c3=(g+8,2t+1)
    #pragma unroll
    for (int mi = 0; mi < 4; mi++) {
        #pragma unroll
        for (int ni = 0; ni < 4; ni++) {
            int col = bn + wn + ni * 8 + 2 * tig;
            float b0v = bias ? bias[col]     : 0.0f;
            float b1v = bias ? bias[col + 1] : 0.0f;
            #pragma unroll
            for (int rr = 0; rr < 2; rr++) {
                int row = bm + wm + mi * 16 + grp + rr * 8;
                float v0 = acc[mi][ni][rr * 2 + 0] * scale + b0v;
                float v1 = acc[mi][ni][rr * 2 + 1] * scale + b1v;
                if (ACT == 1) {
                    v0 = (v0 > 0.0f) ? v0 : 0.1f * v0;
                    v1 = (v1 > 0.0f) ? v1 : 0.1f * v1;
                }
                if (MODE == 0) {
                    size_t off = (size_t)row * Nn + col;
                    if (RES) { v0 += resid[off]; v1 += resid[off + 1]; }
                    *(float2*)(Cf + off) = make_float2(v0, v1);
                } else if (MODE == 1) {
                    size_t off = (size_t)row * Nn + col;
                    *(__half2*)(Ch + off) = __floats2half2_rn(v0, v1);
                } else {
                    Ch[(size_t)col * M + row]       = __float2half_rn(v0);
                    Ch[(size_t)(col + 1) * M + row] = __float2half_rn(v1);
                }
            }
        }
    }
}

static constexpr int SMEM_H = 6 * 128 * 40 * 2;   // 61440 bytes

// ---------------- host side ----------------
extern "C" void kernel_launch(void* const* d_in, const int* in_sizes, int n_in,
                              void* d_out, int out_size) {
    const float* x      = (const float*)d_in[0];
    const float* norm_g = (const float*)d_in[1];
    const float* norm_b = (const float*)d_in[2];
    const float* Wq = (const float*)d_in[3];
    const float* bq = (const float*)d_in[4];
    const float* Wk = (const float*)d_in[5];
    const float* bk = (const float*)d_in[6];
    const float* Wv = (const float*)d_in[7];
    const float* bv = (const float*)d_in[8];
    const float* W1 = (const float*)d_in[9];
    const float* b1 = (const float*)d_in[10];
    const float* W2 = (const float*)d_in[11];
    const float* b2 = (const float*)d_in[12];
    float* out = (float*)d_out;

    float  *xn, *s;
    __half *xnh, *qh, *kh, *vT, *p, *h, *mid;
    __half *wqT, *wkT, *wvT, *w1T, *w2T;
    cudaGetSymbolAddress((void**)&xn,  g_xn);
    cudaGetSymbolAddress((void**)&s,   g_s);
    cudaGetSymbolAddress((void**)&xnh, g_xnh);
    cudaGetSymbolAddress((void**)&qh,  g_qh);
    cudaGetSymbolAddress((void**)&kh,  g_kh);
    cudaGetSymbolAddress((void**)&vT,  g_vT);
    cudaGetSymbolAddress((void**)&p,   g_p);
    cudaGetSymbolAddress((void**)&h,   g_h);
    cudaGetSymbolAddress((void**)&mid, g_mid);
    cudaGetSymbolAddress((void**)&wqT, g_wqT);
    cudaGetSymbolAddress((void**)&wkT, g_wkT);
    cudaGetSymbolAddress((void**)&wvT, g_wvT);
    cudaGetSymbolAddress((void**)&w1T, g_w1T);
    cudaGetSymbolAddress((void**)&w2T, g_w2T);

    cudaFuncSetAttribute(hgemm_kernel<0,0,false>, cudaFuncAttributeMaxDynamicSharedMemorySize, SMEM_H);
    cudaFuncSetAttribute(hgemm_kernel<0,0,true >, cudaFuncAttributeMaxDynamicSharedMemorySize, SMEM_H);
    cudaFuncSetAttribute(hgemm_kernel<1,0,false>, cudaFuncAttributeMaxDynamicSharedMemorySize, SMEM_H);
    cudaFuncSetAttribute(hgemm_kernel<1,1,false>, cudaFuncAttributeMaxDynamicSharedMemorySize, SMEM_H);
    cudaFuncSetAttribute(hgemm_kernel<2,0,false>, cudaFuncAttributeMaxDynamicSharedMemorySize, SMEM_H);

    // 0. weight prep (transpose + fp16) — separate launches (proven path)
    wprep_kernel<<<dim3(ND/32, ND/32), 256>>>(Wq, wqT, ND, ND);
    wprep_kernel<<<dim3(ND/32, ND/32), 256>>>(Wk, wkT, ND, ND);
    wprep_kernel<<<dim3(ND/32, ND/32), 256>>>(Wv, wvT, ND, ND);
    wprep_kernel<<<dim3(FD/32, ND/32), 256>>>(W1, w1T, ND, FD);
    wprep_kernel<<<dim3(ND/32, FD/32), 256>>>(W2, w2T, FD, ND);

    // 1. LayerNorm
    ln_kernel<<<SQ, 256>>>(x, norm_g, norm_b);

    // 2. q/k/v projections  (C = xn @ WT^T), v written transposed
    dim3 gNN(ND/128, SQ/128);           // (8, 32)
    hgemm_kernel<1,0,false><<<gNN, 256, SMEM_H>>>(xnh, wqT, bq, nullptr, nullptr, qh, SQ, ND, ND, 1.0f);
    hgemm_kernel<1,0,false><<<gNN, 256, SMEM_H>>>(xnh, wkT, bk, nullptr, nullptr, kh, SQ, ND, ND, 1.0f);
    hgemm_kernel<2,0,false><<<gNN, 256, SMEM_H>>>(xnh, wvT, bv, nullptr, nullptr, vT, SQ, ND, ND, 1.0f);

    // 3. scores = (k @ q^T)/sqrt(N)  -> fp32 [SQ,SQ]
    dim3 gSS(SQ/128, SQ/128);           // (32, 32)
    hgemm_kernel<0,0,false><<<gSS, 256, SMEM_H>>>(kh, qh, nullptr, nullptr, s, nullptr, SQ, SQ, ND, 0.03125f);

    // 4. softmax -> fp16 probs
    softmax_kernel<<<SQ, 256>>>();

    // 5. h = P @ v   (B = v^T [ND][SQ])
    hgemm_kernel<1,0,false><<<gNN, 256, SMEM_H>>>(p, vT, nullptr, nullptr, nullptr, h, SQ, ND, SQ, 1.0f);

    // 6. mid = leaky_relu(h @ W1 + b1)
    dim3 gNF(FD/128, SQ/128);           // (32, 32)
    hgemm_kernel<1,1,false><<<gNF, 256, SMEM_H>>>(h, w1T, b1, nullptr, nullptr, mid, SQ, FD, ND, 1.0f);

    // 7. out = mid @ W2 + b2 + xn
    hgemm_kernel<0,0,true><<<gNN, 256, SMEM_H>>>(mid, w2T, b2, xn, out, nullptr, SQ, ND, FD, 1.0f);
}

// round 15
// speedup vs baseline: 1.3096x; 1.1977x over previous
#include <cuda_runtime.h>
#include <cuda_fp16.h>
#include <cstdint>

#define SQ 4096      // sequence length S
#define ND 1024      // model dim N
#define FD 4096      // ffn dim 4N

// ---------------- scratch (allocation-free: static device globals) ----------
__device__ float  g_xn [(size_t)SQ * ND];           // fp32 normed x (residual)
__device__ __half g_xnh[(size_t)SQ * ND];           // fp16 normed x (GEMM A)
__device__ __half g_qh [(size_t)SQ * ND];
__device__ __half g_kh [(size_t)SQ * ND];
__device__ __half g_vT [(size_t)ND * SQ];           // v transposed [n][s]
__device__ float  g_s  [(size_t)SQ * SQ];           // fp32 scores
__device__ __half g_p  [(size_t)SQ * SQ];           // fp16 probs
__device__ __half g_h  [(size_t)SQ * ND];
__device__ __half g_mid[(size_t)SQ * FD];
// pre-transposed fp16 weights WT[n][k]
__device__ __half g_wqT[(size_t)ND * ND];
__device__ __half g_wkT[(size_t)ND * ND];
__device__ __half g_wvT[(size_t)ND * ND];
__device__ __half g_w1T[(size_t)FD * ND];
__device__ __half g_w2T[(size_t)ND * FD];

// ---------------- helpers ----------------
__device__ __forceinline__ float warpSum(float v) {
    #pragma unroll
    for (int o = 16; o; o >>= 1) v += __shfl_xor_sync(0xffffffffu, v, o);
    return v;
}
__device__ __forceinline__ float warpMax(float v) {
    #pragma unroll
    for (int o = 16; o; o >>= 1) v = fmaxf(v, __shfl_xor_sync(0xffffffffu, v, o));
    return v;
}
__device__ __forceinline__ void cp_async16(void* smem_dst, const void* gmem_src) {
    uint32_t s = (uint32_t)__cvta_generic_to_shared(smem_dst);
    asm volatile("cp.async.cg.shared.global [%0], [%1], 16;" :: "r"(s), "l"(gmem_src));
}
__device__ __forceinline__ void cp_commit() {
    asm volatile("cp.async.commit_group;" ::: "memory");
}
template<int NN>
__device__ __forceinline__ void cp_wait() {
    asm volatile("cp.async.wait_group %0;" :: "n"(NN) : "memory");
}
__device__ __forceinline__ void mma_f16(float* c, const uint32_t* a, const uint32_t* b) {
    asm volatile(
        "mma.sync.aligned.m16n8k16.row.col.f32.f16.f16.f32 "
        "{%0,%1,%2,%3}, {%4,%5,%6,%7}, {%8,%9}, {%0,%1,%2,%3};"
        : "+f"(c[0]), "+f"(c[1]), "+f"(c[2]), "+f"(c[3])
        : "r"(a[0]), "r"(a[1]), "r"(a[2]), "r"(a[3]), "r"(b[0]), "r"(b[1]));
}

// ---------------- weight prep: W[K,N] fp32 -> WT[N,K] fp16 ------------------
__global__ __launch_bounds__(256) void wprep_kernel(const float* __restrict__ W,
                                                    __half* __restrict__ T,
                                                    int K, int N) {
    __shared__ float tile[32][33];
    int n0 = blockIdx.x * 32;
    int k0 = blockIdx.y * 32;
    int tx = threadIdx.x & 31;
    int ty = threadIdx.x >> 5;     // 0..7
    #pragma unroll
    for (int i = 0; i < 4; i++) {
        int r = ty + i * 8;
        tile[r][tx] = W[(size_t)(k0 + r) * N + n0 + tx];
    }
    __syncthreads();
    #pragma unroll
    for (int i = 0; i < 4; i++) {
        int r = ty + i * 8;
        T[(size_t)(n0 + r) * K + k0 + tx] = __float2half_rn(tile[tx][r]);
    }
}

// ---------------- LayerNorm: fp32 out + fp16 out ----------------------------
__global__ __launch_bounds__(256) void ln_kernel(const float* __restrict__ x,
                                                 const float* __restrict__ g,
                                                 const float* __restrict__ b) {
    int row = blockIdx.x;
    int t = threadIdx.x;
    const float4* xr = (const float4*)(x + (size_t)row * ND);
    float4 xv = xr[t];
    float s1 = xv.x + xv.y + xv.z + xv.w;
    float s2 = xv.x*xv.x + xv.y*xv.y + xv.z*xv.z + xv.w*xv.w;

    __shared__ float shA[8], shB[8];
    s1 = warpSum(s1); s2 = warpSum(s2);
    if ((t & 31) == 0) { shA[t >> 5] = s1; shB[t >> 5] = s2; }
    __syncthreads();
    if (t < 32) {
        float a = (t < 8) ? shA[t] : 0.0f;
        float c = (t < 8) ? shB[t] : 0.0f;
        a = warpSum(a); c = warpSum(c);
        if (t == 0) { shA[0] = a; shB[0] = c; }
    }
    __syncthreads();
    float mu  = shA[0] * (1.0f / ND);
    float var = shB[0] * (1.0f / ND) - mu * mu;
    float rstd = rsqrtf(var + 1e-5f);

    float4 gv = ((const float4*)g)[t];
    float4 bv = ((const float4*)b)[t];
    float4 o;
    o.x = (xv.x - mu) * rstd * gv.x + bv.x;
    o.y = (xv.y - mu) * rstd * gv.y + bv.y;
    o.z = (xv.z - mu) * rstd * gv.z + bv.z;
    o.w = (xv.w - mu) * rstd * gv.w + bv.w;
    size_t idx = (size_t)row * ND + t * 4;
    *(float4*)(g_xn + idx) = o;
    *(__half2*)(g_xnh + idx)     = __floats2half2_rn(o.x, o.y);
    *(__half2*)(g_xnh + idx + 2) = __floats2half2_rn(o.z, o.w);
}

// ---------------- Softmax: fp32 scores -> fp16 probs ------------------------
__global__ __launch_bounds__(256) void softmax_kernel() {
    int row = blockIdx.x;
    int t = threadIdx.x;
    const float4* r = (const float4*)(g_s + (size_t)row * SQ);
    float4 v[4];
    float mx = -1e30f;
    #pragma unroll
    for (int i = 0; i < 4; i++) {
        v[i] = r[t + i * 256];
        mx = fmaxf(mx, fmaxf(fmaxf(v[i].x, v[i].y), fmaxf(v[i].z, v[i].w)));
    }
    __shared__ float shA[8], shB[8];
    mx = warpMax(mx);
    if ((t & 31) == 0) shA[t >> 5] = mx;
    __syncthreads();
    if (t < 32) {
        float a = (t < 8) ? shA[t] : -1e30f;
        a = warpMax(a);
        if (t == 0) shA[0] = a;
    }
    __syncthreads();
    mx = shA[0];

    float sum = 0.0f;
    #pragma unroll
    for (int i = 0; i < 4; i++) {
        v[i].x = __expf(v[i].x - mx);
        v[i].y = __expf(v[i].y - mx);
        v[i].z = __expf(v[i].z - mx);
        v[i].w = __expf(v[i].w - mx);
        sum += v[i].x + v[i].y + v[i].z + v[i].w;
    }
    sum = warpSum(sum);
    if ((t & 31) == 0) shB[t >> 5] = sum;
    __syncthreads();
    if (t < 32) {
        float a = (t < 8) ? shB[t] : 0.0f;
        a = warpSum(a);
        if (t == 0) shB[0] = a;
    }
    __syncthreads();
    float inv = 1.0f / shB[0];
    #pragma unroll
    for (int i = 0; i < 4; i++) {
        size_t idx = (size_t)row * SQ + (t + i * 256) * 4;
        *(__half2*)(g_p + idx)     = __floats2half2_rn(v[i].x * inv, v[i].y * inv);
        *(__half2*)(g_p + idx + 2) = __floats2half2_rn(v[i].z * inv, v[i].w * inv);
    }
}

// ---------------- fp16 tensor-core GEMM (R8 mainloop, BK=64) ----------------
// C[M,Nn] = act(scale*(A @ B^T) + bias) (+resid)
// A [M,K] fp16 row-major, B [Nn,K] fp16 row-major.
// MODE 0: fp32 out Cf (scale, +resid). MODE 1: fp16 out Ch (bias, act).
// MODE 2: fp16 out transposed Ch[col*M + row] (bias).
// Tile: 128x128, 128 threads (4 warps, 64x64 each), BK=64, 3-stage cp.async,
// single __syncthreads per k-tile, scalar-LDS fragments.
template<int MODE, int ACT, bool RES>
__global__ __launch_bounds__(128, 2) void hgemm_kernel(
    const __half* __restrict__ A, const __half* __restrict__ B,
    const float* __restrict__ bias, const float* __restrict__ resid,
    float* __restrict__ Cf, __half* __restrict__ Ch,
    int M, int Nn, int K, float scale)
{
    constexpr int BK = 64;
    constexpr int PITCH = 72;          // smem row pitch in halves (conflict-free)
    constexpr int TST = 128 * PITCH;   // halves per tile-stage

    extern __shared__ __half smem[];
    __half* Asm = smem;
    __half* Bsm = smem + 3 * TST;

    int tid  = threadIdx.x;
    int wid  = tid >> 5;
    int lane = tid & 31;
    int grp  = lane >> 2;
    int tig  = lane & 3;
    int wm = (wid & 1) * 64;
    int wn = (wid >> 1) * 64;
    int bm = blockIdx.y * 128;
    int bn = blockIdx.x * 128;

    float acc[4][8][4];
    #pragma unroll
    for (int i = 0; i < 4; i++)
        #pragma unroll
        for (int j = 0; j < 8; j++)
            #pragma unroll
            for (int c = 0; c < 4; c++) acc[i][j][c] = 0.0f;

    // load one 128x64 tile pair (A and B) into stage s
    auto loadTile = [&](int s, int k0) {
        __half* As = Asm + s * TST;
        __half* Bs = Bsm + s * TST;
        #pragma unroll
        for (int it = 0; it < 8; it++) {
            int idx = tid + it * 128;     // 0..1023
            int r = idx >> 3;             // 0..127
            int ch = (idx & 7) << 3;      // half-offset 0..56
            cp_async16(As + r * PITCH + ch, A + (size_t)(bm + r) * K + k0 + ch);
        }
        #pragma unroll
        for (int it = 0; it < 8; it++) {
            int idx = tid + it * 128;
            int r = idx >> 3;
            int ch = (idx & 7) << 3;
            cp_async16(Bs + r * PITCH + ch, B + (size_t)(bn + r) * K + k0 + ch);
        }
        cp_commit();
    };

    int nt = K / BK;
    loadTile(0, 0);
    loadTile(1, BK);

    int s = 0, sl = 2;
    for (int t = 0; t < nt; t++) {
        if (t + 1 < nt) cp_wait<1>(); else cp_wait<0>();
        __syncthreads();

        const __half* As = Asm + s * TST;
        const __half* Bs = Bsm + s * TST;

        #pragma unroll
        for (int ks = 0; ks < 4; ks++) {
            uint32_t af[4][4];
            uint32_t bf[8][2];
            #pragma unroll
            for (int mi = 0; mi < 4; mi++) {
                const __half* ap = &As[(wm + mi * 16 + grp) * PITCH + ks * 16 + tig * 2];
                af[mi][0] = *(const uint32_t*)(ap);                 // (g,    2t..2t+1)
                af[mi][1] = *(const uint32_t*)(ap + 8 * PITCH);     // (g+8,  2t..2t+1)
                af[mi][2] = *(const uint32_t*)(ap + 8);             // (g,    2t+8..9)
                af[mi][3] = *(const uint32_t*)(ap + 8 * PITCH + 8); // (g+8,  2t+8..9)
            }
            #pragma unroll
            for (int ni = 0; ni < 8; ni++) {
                const __half* bp = &Bs[(wn + ni * 8 + grp) * PITCH + ks * 16 + tig * 2];
                bf[ni][0] = *(const uint32_t*)(bp);                 // (n g, k 2t..2t+1)
                bf[ni][1] = *(const uint32_t*)(bp + 8);             // (n g, k 2t+8..9)
            }
            #pragma unroll
            for (int mi = 0; mi < 4; mi++)
                #pragma unroll
                for (int ni = 0; ni < 8; ni++)
                    mma_f16(acc[mi][ni], af[mi], bf[ni]);
        }

        if (t + 2 < nt) loadTile(sl, (t + 2) * BK);
        s  = (s  == 2) ? 0 : s + 1;
        sl = (sl == 2) ? 0 : sl + 1;
    }

    // epilogue: c0=(g,2t) c1=(g,2t+1) c2=(g+8,2t) c3=(g+8,2t+1)
    #pragma unroll
    for (int mi = 0; mi < 4; mi++) {
        #pragma unroll
        for (int ni = 0; ni < 8; ni++) {
            int col = bn + wn + ni * 8 + 2 * tig;
            float b0v = bias ? bias[col]     : 0.0f;
            float b1v = bias ? bias[col + 1] : 0.0f;
            #pragma unroll
            for (int rr = 0; rr < 2; rr++) {
                int row = bm + wm + mi * 16 + grp + rr * 8;
                float v0 = acc[mi][ni][rr * 2 + 0] * scale + b0v;
                float v1 = acc[mi][ni][rr * 2 + 1] * scale + b1v;
                if (ACT == 1) {
                    v0 = (v0 > 0.0f) ? v0 : 0.1f * v0;
                    v1 = (v1 > 0.0f) ? v1 : 0.1f * v1;
                }
                if (MODE == 0) {
                    size_t off = (size_t)row * Nn + col;
                    if (RES) { v0 += resid[off]; v1 += resid[off + 1]; }
                    *(float2*)(Cf + off) = make_float2(v0, v1);
                } else if (MODE == 1) {
                    size_t off = (size_t)row * Nn + col;
                    *(__half2*)(Ch + off) = __floats2half2_rn(v0, v1);
                } else {
                    Ch[(size_t)col * M + row]       = __float2half_rn(v0);
                    Ch[(size_t)(col + 1) * M + row] = __float2half_rn(v1);
                }
            }
        }
    }
}

static constexpr int SMEM_H = 6 * 128 * 72 * 2;   // 110592 bytes

// ---------------- host side ----------------
extern "C" void kernel_launch(void* const* d_in, const int* in_sizes, int n_in,
                              void* d_out, int out_size) {
    const float* x      = (const float*)d_in[0];
    const float* norm_g = (const float*)d_in[1];
    const float* norm_b = (const float*)d_in[2];
    const float* Wq = (const float*)d_in[3];
    const float* bq = (const float*)d_in[4];
    const float* Wk = (const float*)d_in[5];
    const float* bk = (const float*)d_in[6];
    const float* Wv = (const float*)d_in[7];
    const float* bv = (const float*)d_in[8];
    const float* W1 = (const float*)d_in[9];
    const float* b1 = (const float*)d_in[10];
    const float* W2 = (const float*)d_in[11];
    const float* b2 = (const float*)d_in[12];
    float* out = (float*)d_out;

    float  *xn, *s;
    __half *xnh, *qh, *kh, *vT, *p, *h, *mid;
    __half *wqT, *wkT, *wvT, *w1T, *w2T;
    cudaGetSymbolAddress((void**)&xn,  g_xn);
    cudaGetSymbolAddress((void**)&s,   g_s);
    cudaGetSymbolAddress((void**)&xnh, g_xnh);
    cudaGetSymbolAddress((void**)&qh,  g_qh);
    cudaGetSymbolAddress((void**)&kh,  g_kh);
    cudaGetSymbolAddress((void**)&vT,  g_vT);
    cudaGetSymbolAddress((void**)&p,   g_p);
    cudaGetSymbolAddress((void**)&h,   g_h);
    cudaGetSymbolAddress((void**)&mid, g_mid);
    cudaGetSymbolAddress((void**)&wqT, g_wqT);
    cudaGetSymbolAddress((void**)&wkT, g_wkT);
    cudaGetSymbolAddress((void**)&wvT, g_wvT);
    cudaGetSymbolAddress((void**)&w1T, g_w1T);
    cudaGetSymbolAddress((void**)&w2T, g_w2T);

    cudaFuncSetAttribute(hgemm_kernel<0,0,false>, cudaFuncAttributeMaxDynamicSharedMemorySize, SMEM_H);
    cudaFuncSetAttribute(hgemm_kernel<0,0,true >, cudaFuncAttributeMaxDynamicSharedMemorySize, SMEM_H);
    cudaFuncSetAttribute(hgemm_kernel<1,0,false>, cudaFuncAttributeMaxDynamicSharedMemorySize, SMEM_H);
    cudaFuncSetAttribute(hgemm_kernel<1,1,false>, cudaFuncAttributeMaxDynamicSharedMemorySize, SMEM_H);
    cudaFuncSetAttribute(hgemm_kernel<2,0,false>, cudaFuncAttributeMaxDynamicSharedMemorySize, SMEM_H);

    // 0. weight prep (transpose + fp16)
    wprep_kernel<<<dim3(ND/32, ND/32), 256>>>(Wq, wqT, ND, ND);
    wprep_kernel<<<dim3(ND/32, ND/32), 256>>>(Wk, wkT, ND, ND);
    wprep_kernel<<<dim3(ND/32, ND/32), 256>>>(Wv, wvT, ND, ND);
    wprep_kernel<<<dim3(FD/32, ND/32), 256>>>(W1, w1T, ND, FD);
    wprep_kernel<<<dim3(ND/32, FD/32), 256>>>(W2, w2T, FD, ND);

    // 1. LayerNorm
    ln_kernel<<<SQ, 256>>>(x, norm_g, norm_b);

    // 2. q/k/v projections  (C = xn @ WT^T), v written transposed
    dim3 gNN(ND/128, SQ/128);           // (8, 32)
    hgemm_kernel<1,0,false><<<gNN, 128, SMEM_H>>>(xnh, wqT, bq, nullptr, nullptr, qh, SQ, ND, ND, 1.0f);
    hgemm_kernel<1,0,false><<<gNN, 128, SMEM_H>>>(xnh, wkT, bk, nullptr, nullptr, kh, SQ, ND, ND, 1.0f);
    hgemm_kernel<2,0,false><<<gNN, 128, SMEM_H>>>(xnh, wvT, bv, nullptr, nullptr, vT, SQ, ND, ND, 1.0f);

    // 3. scores = (k @ q^T)/sqrt(N)  -> fp32 [SQ,SQ]
    dim3 gSS(SQ/128, SQ/128);           // (32, 32)
    hgemm_kernel<0,0,false><<<gSS, 128, SMEM_H>>>(kh, qh, nullptr, nullptr, s, nullptr, SQ, SQ, ND, 0.03125f);

    // 4. softmax -> fp16 probs
    softmax_kernel<<<SQ, 256>>>();

    // 5. h = P @ v   (B = v^T [ND][SQ])
    hgemm_kernel<1,0,false><<<gNN, 128, SMEM_H>>>(p, vT, nullptr, nullptr, nullptr, h, SQ, ND, SQ, 1.0f);

    // 6. mid = leaky_relu(h @ W1 + b1)
    dim3 gNF(FD/128, SQ/128);           // (32, 32)
    hgemm_kernel<1,1,false><<<gNF, 128, SMEM_H>>>(h, w1T, b1, nullptr, nullptr, mid, SQ, FD, ND, 1.0f);

    // 7. out = mid @ W2 + b2 + xn
    hgemm_kernel<0,0,true><<<gNN, 128, SMEM_H>>>(mid, w2T, b2, xn, out, nullptr, SQ, ND, FD, 1.0f);
}